// round 5
// baseline (speedup 1.0000x reference)
#include <cuda_runtime.h>

// Lower-triangular matvec: y[i] = sum_{j<=i} W[i,j] * x[j]
// n = 8192, W row-major fp32 (lower triangle = 128 MB, streamed once).
//
// R5: one row PAIR (i, n-1-i) per WARP. Every warp does exactly n+1
// W-elements (perfect balance), the whole grid is ONE resident wave
// (512 blocks x 8 warps = 4096 warps ~ 28/SM), and there are no block
// barriers at all -- the reduction is warp-shuffle only. This removes the
// per-block ramp-down + barrier overhead that capped R2 at 62.6% DRAM.
// W: LDG.128 __ldcs (read-once, evict-first), 4x unrolled. x: __ldg (L1-hit).

#define NTHREADS 256
#define WARPS_PER_BLOCK (NTHREADS / 32)

__device__ __forceinline__ float dot4(float4 w, float4 v) {
    return w.x * v.x + w.y * v.y + w.z * v.z + w.w * v.w;
}

// Per-lane partial dot of W row (length len) with x. Lane-strided float4s.
__device__ __forceinline__ float row_dot_warp(const float* __restrict__ Wr,
                                              const float4* __restrict__ x4,
                                              const float* __restrict__ x,
                                              int len, int lane)
{
    const float4* __restrict__ W4 = reinterpret_cast<const float4*>(Wr);
    const int nv4 = len >> 2;

    float a0 = 0.0f, a1 = 0.0f, a2 = 0.0f, a3 = 0.0f;

    int k = lane;
    for (; k + 96 < nv4; k += 128) {
        float4 w0 = __ldcs(W4 + k);
        float4 w1 = __ldcs(W4 + k + 32);
        float4 w2 = __ldcs(W4 + k + 64);
        float4 w3 = __ldcs(W4 + k + 96);
        float4 v0 = __ldg(x4 + k);
        float4 v1 = __ldg(x4 + k + 32);
        float4 v2 = __ldg(x4 + k + 64);
        float4 v3 = __ldg(x4 + k + 96);
        a0 += dot4(w0, v0);
        a1 += dot4(w1, v1);
        a2 += dot4(w2, v2);
        a3 += dot4(w3, v3);
    }
    #pragma unroll 1
    for (; k < nv4; k += 32) {
        a0 += dot4(__ldcs(W4 + k), __ldg(x4 + k));
    }

    float acc = (a0 + a1) + (a2 + a3);

    // Scalar tail (len % 4 elements).
    const int tail = len & 3;
    if (lane < tail) {
        const int j = (nv4 << 2) + lane;
        acc += Wr[j] * x[j];
    }
    return acc;
}

__global__ __launch_bounds__(NTHREADS)
void tril_mv_kernel(const float* __restrict__ x,
                    const float* __restrict__ W,
                    float* __restrict__ y,
                    int n)
{
    const int lane = threadIdx.x & 31;
    const int w    = (blockIdx.x * WARPS_PER_BLOCK) + (threadIdx.x >> 5);
    // w in [0, n/2): this warp owns rows r0 = w and r1 = n-1-w.
    const int r0 = w;
    const int r1 = n - 1 - w;

    const float4* __restrict__ x4 = reinterpret_cast<const float4*>(x);

    float acc0 = row_dot_warp(W + (size_t)r0 * n, x4, x, r0 + 1, lane);
    float acc1 = row_dot_warp(W + (size_t)r1 * n, x4, x, r1 + 1, lane);

    // Warp-only reduction (no barriers anywhere in the kernel).
    #pragma unroll
    for (int off = 16; off > 0; off >>= 1) {
        acc0 += __shfl_down_sync(0xffffffffu, acc0, off);
        acc1 += __shfl_down_sync(0xffffffffu, acc1, off);
    }
    if (lane == 0) {
        y[r0] = acc0;
        y[r1] = acc1;
    }
}

extern "C" void kernel_launch(void* const* d_in, const int* in_sizes, int n_in,
                              void* d_out, int out_size) {
    const float* x = (const float*)d_in[0];   // [n]
    const float* W = (const float*)d_in[1];   // [n, n] row-major
    float*       y = (float*)d_out;           // [n]

    const int n = in_sizes[0];                // 8192 (even)
    const int npairs = n / 2;                 // 4096 warps
    const int grid = npairs / WARPS_PER_BLOCK;

    tril_mv_kernel<<<grid, NTHREADS>>>(x, W, y, n);
}